// round 6
// baseline (speedup 1.0000x reference)
#include <cuda_runtime.h>
#include <cuda_bf16.h>
#include <math.h>

// ---------------------------------------------------------------------------
// DKVMN: B=64, L=200, D=128, M=50, FIX=512. Rows = 12800.
//   kpath : k = k_emb[q]@W1+b1                      (64x128 tile GEMM K=512)
//   vea   : v = v_emb[q+1e4r]@W2+b2 (smem only);
//           e = sigmoid(v@We+be); a = tanh(v@Wa+ba)
//   wsoftmax : w = softmax(k@Mk^T)
//   scan  : r_t = w_t.Mv ; Mv += w (x) (a - e*Mv)
//   head  : p = sigmoid(tanh([reads|k]@Wf+bf)@Wp+bp)
// All GEMM CTAs: 128 threads (4 warps -> all 4 SMSPs), 8x8 per thread.
// ---------------------------------------------------------------------------

#define NROWS 12800

__device__ float g_k[NROWS * 128];
__device__ float g_e[NROWS * 128];
__device__ float g_a[NROWS * 128];
__device__ float g_reads[NROWS * 128];
__device__ float g_w[NROWS * 64];   // pitch 64, 50 valid

__device__ __forceinline__ float fast_tanh(float x) {
    float y;
    asm("tanh.approx.f32 %0, %1;" : "=f"(y) : "f"(x));
    return y;
}
__device__ __forceinline__ float fast_sig(float x) {
    return 0.5f * fast_tanh(0.5f * x) + 0.5f;
}

// ---------------------------------------------------------------------------
// Shared 64x128 mainloop: 128 threads, 8x8/thread, BK=16, double-buffered.
// aA/aB: per-thread row base pointers (row lrow = t>>1); cols kt*16 + ...
// For kt >= SPLIT read aB (concat case). W row-major [K,128].
// ---------------------------------------------------------------------------
template <int NT, int SPLIT>
__device__ __forceinline__ void mm64x128(
    const float* __restrict__ aA, const float* __restrict__ aB,
    const float* __restrict__ W, float (&acc)[8][8],
    float (*As)[16][68], float (*Bs)[16][132], int t)
{
    const int lrow = t >> 1;
    const int c4b  = (t & 1) * 2;
    const int cx = t & 15, ry = t >> 4;

    float4 ar[2], br[4];
    auto ldA = [&](int kt) {
        const float* base = (kt < SPLIT) ? (aA + kt * 16) : (aB + (kt - SPLIT) * 16);
#pragma unroll
        for (int u = 0; u < 2; ++u)
            ar[u] = *reinterpret_cast<const float4*>(base + (c4b + u) * 4);
    };
    auto ldB = [&](int kt) {
#pragma unroll
        for (int u = 0; u < 4; ++u) {
            int e = t + u * 128;
            int rr = e >> 5, cb = e & 31;
            br[u] = *reinterpret_cast<const float4*>(W + (size_t)(kt * 16 + rr) * 128 + cb * 4);
        }
    };
    auto stAB = [&](int buf) {
#pragma unroll
        for (int u = 0; u < 2; ++u) {
            int kkb = (c4b + u) * 4;
            As[buf][kkb + 0][lrow] = ar[u].x;
            As[buf][kkb + 1][lrow] = ar[u].y;
            As[buf][kkb + 2][lrow] = ar[u].z;
            As[buf][kkb + 3][lrow] = ar[u].w;
        }
#pragma unroll
        for (int u = 0; u < 4; ++u) {
            int e = t + u * 128;
            int rr = e >> 5, cb = e & 31;
            *reinterpret_cast<float4*>(&Bs[buf][rr][cb * 4]) = br[u];
        }
    };

    ldA(0); ldB(0); stAB(0);
    __syncthreads();

#pragma unroll 1
    for (int kt = 0; kt < NT; ++kt) {
        const int cur = kt & 1, nxt = cur ^ 1;
        if (kt + 1 < NT) { ldA(kt + 1); ldB(kt + 1); }
#pragma unroll
        for (int kk = 0; kk < 16; ++kk) {
            float4 a0 = *reinterpret_cast<const float4*>(&As[cur][kk][ry * 8]);
            float4 a1 = *reinterpret_cast<const float4*>(&As[cur][kk][ry * 8 + 4]);
            float4 b0 = *reinterpret_cast<const float4*>(&Bs[cur][kk][cx * 8]);
            float4 b1 = *reinterpret_cast<const float4*>(&Bs[cur][kk][cx * 8 + 4]);
            float aa[8] = {a0.x, a0.y, a0.z, a0.w, a1.x, a1.y, a1.z, a1.w};
            float bb[8] = {b0.x, b0.y, b0.z, b0.w, b1.x, b1.y, b1.z, b1.w};
#pragma unroll
            for (int i = 0; i < 8; ++i)
#pragma unroll
                for (int j = 0; j < 8; ++j)
                    acc[i][j] = fmaf(aa[i], bb[j], acc[i][j]);
        }
        if (kt + 1 < NT) stAB(nxt);
        __syncthreads();
    }
}

// ---------------------------------------------------------------------------
// kpath: k = k_emb[q]@W1 + b1, 64-row tiles.
// ---------------------------------------------------------------------------
__global__ __launch_bounds__(128) void kpath_kernel(
    const float* __restrict__ k_emb, const int* __restrict__ q,
    const float* __restrict__ W1, const float* __restrict__ b1,
    float* __restrict__ gk)
{
    __shared__ float As[2][16][68];
    __shared__ float Bs[2][16][132];
    const int t = threadIdx.x, mb = blockIdx.x;
    const int cx = t & 15, ry = t >> 4;
    const int lrow = t >> 1;
    const float* aA = k_emb + (size_t)q[mb * 64 + lrow] * 512;

    float acc[8][8];
#pragma unroll
    for (int i = 0; i < 8; i++)
#pragma unroll
        for (int j = 0; j < 8; j++) acc[i][j] = 0.f;

    mm64x128<32, 32>(aA, nullptr, W1, acc, As, Bs, t);

#pragma unroll
    for (int i = 0; i < 8; ++i) {
        size_t row = (size_t)(mb * 64 + ry * 8 + i);
        float o[8];
#pragma unroll
        for (int j = 0; j < 8; ++j) o[j] = acc[i][j] + b1[cx * 8 + j];
        float* dst = gk + row * 128 + cx * 8;
        *reinterpret_cast<float4*>(dst)     = make_float4(o[0], o[1], o[2], o[3]);
        *reinterpret_cast<float4*>(dst + 4) = make_float4(o[4], o[5], o[6], o[7]);
    }
}

// ---------------------------------------------------------------------------
// vea: v = v_emb[q+10000r]@W2+b2 -> smem; e = sigmoid(v@We+be); a = tanh(v@Wa+ba)
// smem: mainloop union { As+Bs } then { Vs[64][132] ; Bs1[16][132] }.
// ---------------------------------------------------------------------------
struct VeaMain { float As[2][16][68]; float Bs[2][16][132]; };
struct VeaPhase2 { float Vs[64][132]; float Bs1[16][132]; };
union VeaSmem { VeaMain m; VeaPhase2 p; };

__global__ __launch_bounds__(128) void vea_kernel(
    const float* __restrict__ v_emb, const int* __restrict__ q,
    const int* __restrict__ r, const float* __restrict__ W2,
    const float* __restrict__ b2, const float* __restrict__ We,
    const float* __restrict__ be, const float* __restrict__ Wa,
    const float* __restrict__ ba, float* __restrict__ ge,
    float* __restrict__ ga)
{
    __shared__ VeaSmem s;
    const int t = threadIdx.x, mb = blockIdx.x;
    const int cx = t & 15, ry = t >> 4;
    const int lrow = t >> 1;
    const int grow = mb * 64 + lrow;
    const size_t arow = (size_t)q[grow] + (size_t)10000 * (size_t)r[grow];
    const float* aA = v_emb + arow * 512;

    float acc[8][8];
#pragma unroll
    for (int i = 0; i < 8; i++)
#pragma unroll
        for (int j = 0; j < 8; j++) acc[i][j] = 0.f;

    mm64x128<32, 32>(aA, nullptr, W2, acc, s.m.As, s.m.Bs, t);

    // after last barrier of mainloop, repurpose smem: write v tile (+b2)
#pragma unroll
    for (int i = 0; i < 8; ++i)
#pragma unroll
        for (int j = 0; j < 8; ++j)
            s.p.Vs[ry * 8 + i][cx * 8 + j] = acc[i][j] + b2[cx * 8 + j];
    __syncthreads();

    // two K=128 passes from smem-A, single-buffered B
#pragma unroll 1
    for (int pass = 0; pass < 2; ++pass) {
        const float* W  = pass ? Wa : We;
        const float* bb = pass ? ba : be;
        float* dst      = pass ? ga : ge;

#pragma unroll
        for (int i = 0; i < 8; i++)
#pragma unroll
            for (int j = 0; j < 8; j++) acc[i][j] = 0.f;

#pragma unroll 1
        for (int kt = 0; kt < 8; ++kt) {
#pragma unroll
            for (int u = 0; u < 4; ++u) {
                int e = t + u * 128;
                int rr = e >> 5, cb = e & 31;
                *reinterpret_cast<float4*>(&s.p.Bs1[rr][cb * 4]) =
                    *reinterpret_cast<const float4*>(W + (size_t)(kt * 16 + rr) * 128 + cb * 4);
            }
            __syncthreads();
#pragma unroll
            for (int kk = 0; kk < 16; ++kk) {
                float aa[8];
#pragma unroll
                for (int i = 0; i < 8; ++i) aa[i] = s.p.Vs[ry * 8 + i][kt * 16 + kk];
                float4 b0 = *reinterpret_cast<const float4*>(&s.p.Bs1[kk][cx * 8]);
                float4 b1 = *reinterpret_cast<const float4*>(&s.p.Bs1[kk][cx * 8 + 4]);
                float bb2[8] = {b0.x, b0.y, b0.z, b0.w, b1.x, b1.y, b1.z, b1.w};
#pragma unroll
                for (int i = 0; i < 8; ++i)
#pragma unroll
                    for (int j = 0; j < 8; ++j)
                        acc[i][j] = fmaf(aa[i], bb2[j], acc[i][j]);
            }
            __syncthreads();
        }

#pragma unroll
        for (int i = 0; i < 8; ++i) {
            size_t row = (size_t)(mb * 64 + ry * 8 + i);
            float o[8];
#pragma unroll
            for (int j = 0; j < 8; ++j) {
                float vv = acc[i][j] + bb[cx * 8 + j];
                o[j] = pass ? fast_tanh(vv) : fast_sig(vv);
            }
            float* d = dst + row * 128 + cx * 8;
            *reinterpret_cast<float4*>(d)     = make_float4(o[0], o[1], o[2], o[3]);
            *reinterpret_cast<float4*>(d + 4) = make_float4(o[4], o[5], o[6], o[7]);
        }
    }
}

// ---------------------------------------------------------------------------
// head: 64x128 tile, K=256 ([reads|k]); fused p = sigmoid(tanh(f).Wp + bp).
// ---------------------------------------------------------------------------
__global__ __launch_bounds__(128) void head_kernel(
    const float* __restrict__ reads, const float* __restrict__ k,
    const float* __restrict__ Wf, const float* __restrict__ bf,
    const float* __restrict__ Wp, const float* __restrict__ bp,
    float* __restrict__ out)
{
    __shared__ float As[2][16][68];
    __shared__ float Bs[2][16][132];
    __shared__ float pbuf[64][17];

    const int t = threadIdx.x, mb = blockIdx.x;
    const int cx = t & 15, ry = t >> 4;
    const int lrow = t >> 1;
    const float* aR = reads + (size_t)(mb * 64 + lrow) * 128;
    const float* aK = k     + (size_t)(mb * 64 + lrow) * 128;

    float acc[8][8];
#pragma unroll
    for (int i = 0; i < 8; i++)
#pragma unroll
        for (int j = 0; j < 8; j++) acc[i][j] = 0.f;

    mm64x128<16, 8>(aR, aK, Wf, acc, As, Bs, t);

#pragma unroll
    for (int i = 0; i < 8; ++i) {
        float pac = 0.f;
#pragma unroll
        for (int j = 0; j < 8; ++j) {
            int c = cx * 8 + j;
            float f = fast_tanh(acc[i][j] + bf[c]);
            pac = fmaf(f, Wp[c], pac);
        }
        pbuf[ry * 8 + i][cx] = pac;
    }
    __syncthreads();
    if (t < 64) {
        float sum = bp[0];
#pragma unroll
        for (int x = 0; x < 16; ++x) sum += pbuf[t][x];
        out[mb * 64 + t] = 1.f / (1.f + __expf(-sum));
    }
}

// ---------------------------------------------------------------------------
// w = softmax(k @ Mk^T) : 32 rows/CTA, 128 threads (static smem).
// ---------------------------------------------------------------------------
__global__ __launch_bounds__(128) void wsoftmax_kernel(
    const float* __restrict__ K, const float* __restrict__ Mk,
    float* __restrict__ Wout)
{
    __shared__ float sm_k[32 * 132];
    __shared__ float sm_m[50 * 132];
    float4* kt4 = reinterpret_cast<float4*>(sm_k);
    float4* mk4 = reinterpret_cast<float4*>(sm_m);
    float*  lg  = sm_k;

    const int t  = threadIdx.x;
    const int bi = blockIdx.x;

    for (int e = t; e < 32 * 32; e += 128) {
        int rw = e >> 5, c4 = e & 31;
        kt4[rw * 33 + c4] =
            *reinterpret_cast<const float4*>(K + ((size_t)(bi * 32 + rw)) * 128 + c4 * 4);
    }
    for (int e = t; e < 50 * 32; e += 128) {
        int m = e >> 5, c4 = e & 31;
        mk4[m * 33 + c4] = *reinterpret_cast<const float4*>(Mk + (size_t)m * 128 + c4 * 4);
    }
    __syncthreads();

    const int row = t >> 2;
    const int mg  = t & 3;
    const int m0  = (mg < 2) ? mg * 13 : 26 + (mg - 2) * 12;
    const int cnt = (mg < 2) ? 13 : 12;

    float s[13];
#pragma unroll
    for (int j = 0; j < 13; j++) s[j] = 0.f;

    for (int c4 = 0; c4 < 32; ++c4) {
        float4 kv = kt4[row * 33 + c4];
#pragma unroll
        for (int j = 0; j < 13; j++) {
            if (j < cnt) {
                float4 mv = mk4[(m0 + j) * 33 + c4];
                s[j] = fmaf(kv.x, mv.x, fmaf(kv.y, mv.y,
                        fmaf(kv.z, mv.z, fmaf(kv.w, mv.w, s[j]))));
            }
        }
    }
    __syncthreads();
#pragma unroll
    for (int j = 0; j < 13; j++)
        if (j < cnt) lg[row * 52 + m0 + j] = s[j];
    __syncthreads();

    if (t < 32) {
        float mx = -1e30f;
        for (int m = 0; m < 50; m++) mx = fmaxf(mx, lg[t * 52 + m]);
        float sum = 0.f;
        for (int m = 0; m < 50; m++) sum += __expf(lg[t * 52 + m] - mx);
        float inv = 1.f / sum;
        size_t ob = (size_t)(bi * 32 + t) * 64;
        for (int m = 0; m < 50; m++)
            Wout[ob + m] = __expf(lg[t * 52 + m] - mx) * inv;
    }
}

// ---------------------------------------------------------------------------
// Scan: grid (4,64), 128 threads; t = dl*4+mg; shfl cross-m reduce; prefetch.
// ---------------------------------------------------------------------------
__global__ __launch_bounds__(128) void scan_kernel(
    const float* __restrict__ Wm, const float* __restrict__ E,
    const float* __restrict__ Aa, const float* __restrict__ Mv0,
    float* __restrict__ R)
{
    const int b  = blockIdx.y;
    const int dc = blockIdx.x;
    const int t  = threadIdx.x;
    const int mg = t & 3;
    const int dl = t >> 2;
    const int d  = dc * 32 + dl;
    const int m0  = (mg < 2) ? mg * 13 : 26 + (mg - 2) * 12;
    const int cnt = (mg < 2) ? 13 : 12;

    float mv[13];
#pragma unroll
    for (int i = 0; i < 13; i++)
        if (i < cnt) mv[i] = Mv0[(size_t)(m0 + i) * 128 + d];

    __shared__ float ws[2][52];

    const size_t rowbase = (size_t)b * 200;
    const float* Ep = E  + rowbase * 128 + d;
    const float* Ap = Aa + rowbase * 128 + d;
    const float* Wp = Wm + rowbase * 64;
    float*       Rp = R  + rowbase * 128 + d;

    float ed, ad, wn = 0.f, en, an;
    if (t < 50) ws[0][t] = Wp[t];
    ed = Ep[0]; ad = Ap[0];
    __syncthreads();

    for (int tt = 0; tt < 200; ++tt) {
        const int pb = tt & 1;
        if (tt < 199) {
            if (t < 50) wn = Wp[(size_t)(tt + 1) * 64 + t];
            en = Ep[(size_t)(tt + 1) * 128];
            an = Ap[(size_t)(tt + 1) * 128];
        }

        float partial = 0.f;
#pragma unroll
        for (int i = 0; i < 13; i++)
            if (i < cnt) partial = fmaf(ws[pb][m0 + i], mv[i], partial);
        partial += __shfl_xor_sync(0xffffffffu, partial, 1);
        partial += __shfl_xor_sync(0xffffffffu, partial, 2);
        if (mg == 0) Rp[(size_t)tt * 128] = partial;

#pragma unroll
        for (int i = 0; i < 13; i++) {
            if (i < cnt) {
                float wm = ws[pb][m0 + i];
                mv[i] = fmaf(wm, fmaf(-mv[i], ed, ad), mv[i]);
            }
        }

        if (tt < 199) {
            if (t < 50) ws[pb ^ 1][t] = wn;
            ed = en; ad = an;
        }
        __syncthreads();
    }
}

// ---------------------------------------------------------------------------
extern "C" void kernel_launch(void* const* d_in, const int* in_sizes, int n_in,
                              void* d_out, int out_size)
{
    const int*   q     = (const int*)d_in[0];
    const int*   r     = (const int*)d_in[1];
    // d_in[2] = diff (unused)
    const float* k_emb = (const float*)d_in[3];
    const float* v_emb = (const float*)d_in[4];
    const float* W1 = (const float*)d_in[5];
    const float* b1 = (const float*)d_in[6];
    const float* W2 = (const float*)d_in[7];
    const float* b2 = (const float*)d_in[8];
    const float* Mk  = (const float*)d_in[9];
    const float* Mv0 = (const float*)d_in[10];
    const float* We = (const float*)d_in[11];
    const float* be = (const float*)d_in[12];
    const float* Wa = (const float*)d_in[13];
    const float* ba = (const float*)d_in[14];
    const float* Wf = (const float*)d_in[15];
    const float* bf = (const float*)d_in[16];
    const float* Wp = (const float*)d_in[17];
    const float* bp = (const float*)d_in[18];
    float* out = (float*)d_out;

    float *pk, *pe, *pa, *pr, *pw;
    cudaGetSymbolAddress((void**)&pk, g_k);
    cudaGetSymbolAddress((void**)&pe, g_e);
    cudaGetSymbolAddress((void**)&pa, g_a);
    cudaGetSymbolAddress((void**)&pr, g_reads);
    cudaGetSymbolAddress((void**)&pw, g_w);

    kpath_kernel<<<200, 128>>>(k_emb, q, W1, b1, pk);
    vea_kernel<<<200, 128>>>(v_emb, q, r, W2, b2, We, be, Wa, ba, pe, pa);
    wsoftmax_kernel<<<400, 128>>>(pk, Mk, pw);
    scan_kernel<<<dim3(4, 64), 128>>>(pw, pe, pa, Mv0, pr);
    head_kernel<<<200, 128>>>(pr, pk, Wf, bf, Wp, bp, out);
}